// round 13
// baseline (speedup 1.0000x reference)
#include <cuda_runtime.h>
#include <cstdint>

#define BATCH 32
#define CH    512
#define NGRP  16
#define CPG   32
#define NTOK  1024
#define GSIZE (CPG * NTOK)

#define NSTAGE 3
#define STG_A  36864                        // max(256*36, 32*264)*4
#define STG_B  18432                        // max(128*36, 32*136)*4
#define SMEM_TOTAL (NSTAGE * (STG_A + STG_B))   // 165888 B

// ---------------- scratch (static device globals; runtime alloc forbidden) -------
__device__ float g_hn [(size_t)BATCH * CH * NTOK];      // (b, c, n) channel-major, tf32
__device__ float g_qkv[(size_t)BATCH * 3 * CH * NTOK];  // (b, {q,k,v}, c, n), tf32
__device__ float g_s  [(size_t)BATCH * NTOK * NTOK];    // exp(scores), tf32
__device__ float g_o  [(size_t)BATCH * CH * NTOK];
__device__ float g_w  [4 * CH * CH];                    // tf32-rounded wq|wk|wv|wp
__device__ float g_bqkv[3 * CH];
__device__ float g_rinv[(size_t)BATCH * NTOK];          // 1 / rowsum(exp)

// ---------------- helpers ---------------------------------------------------------
__device__ __forceinline__ float tf32r(float x) {
    uint32_t u;
    asm("cvt.rna.tf32.f32 %0, %1;" : "=r"(u) : "f"(x));
    return __uint_as_float(u);
}
__device__ __forceinline__ float4 tf32x4(float4 v) {
    v.x = tf32r(v.x); v.y = tf32r(v.y); v.z = tf32r(v.z); v.w = tf32r(v.w);
    return v;
}
__device__ __forceinline__ void cpa16(uint32_t s, const void* g) {
    asm volatile("cp.async.cg.shared.global [%0], [%1], 16;" :: "r"(s), "l"(g));
}
__device__ __forceinline__ uint32_t smem_u32(const void* p) {
    uint32_t a;
    asm("{ .reg .u64 t; cvta.to.shared.u64 t, %1; cvt.u32.u64 %0, t; }" : "=r"(a) : "l"(p));
    return a;
}
__device__ __forceinline__ void mma8(float c[4],
    uint32_t a0, uint32_t a1, uint32_t a2, uint32_t a3, uint32_t b0, uint32_t b1)
{
    asm volatile(
        "mma.sync.aligned.m16n8k8.row.col.f32.tf32.tf32.f32 "
        "{%0,%1,%2,%3}, {%4,%5,%6,%7}, {%8,%9}, {%0,%1,%2,%3};"
        : "+f"(c[0]), "+f"(c[1]), "+f"(c[2]), "+f"(c[3])
        : "r"(a0), "r"(a1), "r"(a2), "r"(a3), "r"(b0), "r"(b1));
}
__device__ __forceinline__ uint32_t fbits(float x) { return __float_as_uint(x); }

// ---------------- setup kernels ----------------------------------------------------
__global__ __launch_bounds__(256) void round_weights(
    const float* __restrict__ wq, const float* __restrict__ wk,
    const float* __restrict__ wv, const float* __restrict__ wp,
    float* __restrict__ w)
{
    int i = blockIdx.x * 256 + threadIdx.x;   // 4 * 65536 float4s
    int m = i >> 16, j = i & 65535;
    const float* src = (m == 0) ? wq : (m == 1) ? wk : (m == 2) ? wv : wp;
    ((float4*)(w + (size_t)m * CH * CH))[j] = tf32x4(((const float4*)src)[j]);
}
__global__ __launch_bounds__(512) void stack_bias(
    const float* __restrict__ bq, const float* __restrict__ bk,
    const float* __restrict__ bv, float* __restrict__ dst)
{
    int i = threadIdx.x;
    dst[i] = bq[i]; dst[CH + i] = bk[i]; dst[2 * CH + i] = bv[i];
}

// ---------------- GroupNorm (channel-major out, tf32-rounded) ---------------------
__global__ __launch_bounds__(256) void groupnorm_kernel(
    const float* __restrict__ x, const float* __restrict__ gamma,
    const float* __restrict__ beta, float* __restrict__ hn)
{
    int b = blockIdx.x / NGRP;
    int g = blockIdx.x % NGRP;
    const float* xp = x  + ((size_t)b * CH + g * CPG) * NTOK;
    float*       hp = hn + ((size_t)b * CH + g * CPG) * NTOK;
    int tid = threadIdx.x;

    float s = 0.f, s2 = 0.f;
    for (int i = tid; i < GSIZE; i += 256) {
        float v = xp[i];
        s += v; s2 += v * v;
    }
    __shared__ float rs[256], rs2[256];
    rs[tid] = s; rs2[tid] = s2;
    __syncthreads();
    for (int o = 128; o > 0; o >>= 1) {
        if (tid < o) { rs[tid] += rs[tid + o]; rs2[tid] += rs2[tid + o]; }
        __syncthreads();
    }
    float mean = rs[0] * (1.0f / GSIZE);
    float var  = rs2[0] * (1.0f / GSIZE) - mean * mean;
    float rstd = rsqrtf(var + 1e-6f);

    for (int i = tid * 4; i < GSIZE; i += 1024) {
        int c = g * CPG + i / NTOK;
        float gm = gamma[c], bt = beta[c];
        float4 v = *(const float4*)&xp[i];
        v.x = tf32r((v.x - mean) * rstd * gm + bt);
        v.y = tf32r((v.y - mean) * rstd * gm + bt);
        v.z = tf32r((v.z - mean) * rstd * gm + bt);
        v.w = tf32r((v.w - mean) * rstd * gm + bt);
        *(float4*)&hp[i] = v;
    }
}

// ---------------- row sum of exp-scores -> reciprocal -----------------------------
__global__ __launch_bounds__(256) void rowsum_recip(const float* __restrict__ e,
                                                    float* __restrict__ rinv)
{
    int row  = blockIdx.x * 8 + (threadIdx.x >> 5);   // one warp per row
    int lane = threadIdx.x & 31;
    const float4* p = (const float4*)(e + (size_t)row * NTOK);
    float s = 0.f;
#pragma unroll
    for (int j = 0; j < 8; j++) {
        float4 v = p[lane + 32 * j];
        s += (v.x + v.y) + (v.z + v.w);
    }
#pragma unroll
    for (int o = 16; o > 0; o >>= 1) s += __shfl_xor_sync(0xFFFFFFFFu, s, o);
    if (lane == 0) rinv[row] = 1.0f / s;
}

// ---------------- tf32 mma.sync batched GEMM ---------------------------------------
// Block tile 256x128, 8 warps (4x2), warp tile 64x64, K-step 32, 3-stage cp.async.
// TA: A row-major [M][K] -> SMEM m-major [256][36]; else [K][M] -> k-major [32][264].
// TB: B row-major [N][K] -> SMEM m-major [128][36]; else [K][N] -> k-major [32][136].
// expOut: C = exp(acc*scale); colscale: C *= colscale[bz*NTOK + n].
// All inputs must already be tf32-rounded in gmem (raw cp.async copies).
template<bool TA, bool TB>
__global__ __launch_bounds__(256, 1) void gemm_cp(
    const float* __restrict__ A, long strideA, int lda,
    const float* __restrict__ B, long strideB, int ldb,
    float* __restrict__ C, long strideC, int ldc,
    int K, const float* __restrict__ bias, const float* __restrict__ resid,
    const float* __restrict__ colscale, float scale, int roundOut, int expOut)
{
    extern __shared__ char smem[];
    const uint32_t sbase = smem_u32(smem);

    const int bz = blockIdx.z;
    const int m0 = blockIdx.y * 256, n0 = blockIdx.x * 128;
    const float* Ab = A + (size_t)bz * strideA;
    const float* Bb = B + (size_t)bz * strideB;

    const int tid  = threadIdx.x;
    const int lane = tid & 31, warp = tid >> 5;
    const int wm = warp >> 1, wn = warp & 1;      // 4 x 2 warp grid, 64 x 64 warp tile
    const int g  = lane >> 2, tg = lane & 3;

    float acc[4][8][4];
#pragma unroll
    for (int i = 0; i < 4; i++)
#pragma unroll
        for (int j = 0; j < 8; j++)
#pragma unroll
            for (int c = 0; c < 4; c++) acc[i][j][c] = 0.f;

    const int nsteps = K / 32;

    auto issue = [&](int step, int s) {
        const uint32_t sa  = sbase + s * STG_A;
        const uint32_t sbb = sbase + NSTAGE * STG_A + s * STG_B;
        const int k0 = step * 32;
#pragma unroll
        for (int i = 0; i < 8; i++) {             // A: 256x32 floats = 2048 x 16B
            int idx = tid + i * 256;
            if (TA) { int m = idx >> 3, kq = idx & 7;
                cpa16(sa + m * 144 + kq * 16,
                      Ab + (size_t)(m0 + m) * lda + k0 + kq * 4); }
            else    { int kk = idx >> 6, m4 = idx & 63;
                cpa16(sa + kk * 1056 + m4 * 16,
                      Ab + (size_t)(k0 + kk) * lda + m0 + m4 * 4); }
        }
#pragma unroll
        for (int i = 0; i < 4; i++) {             // B: 128x32 floats = 1024 x 16B
            int idx = tid + i * 256;
            if (TB) { int n = idx >> 3, kq = idx & 7;
                cpa16(sbb + n * 144 + kq * 16,
                      Bb + (size_t)(n0 + n) * ldb + k0 + kq * 4); }
            else    { int kk = idx >> 5, n4 = idx & 31;
                cpa16(sbb + kk * 544 + n4 * 16,
                      Bb + (size_t)(k0 + kk) * ldb + n0 + n4 * 4); }
        }
        asm volatile("cp.async.commit_group;" ::: "memory");
    };

    // fragment double buffers (two kk-halves in flight)
    uint32_t fa[2][4][4];
    uint32_t fb[2][8][2];

    auto ldfrags = [&](const float* SA, const float* SB, int kk, int h) {
#pragma unroll
        for (int mi = 0; mi < 4; mi++) {
            int mb = wm * 64 + mi * 16;
            if (TA) {
                fa[h][mi][0] = fbits(SA[(mb + g)     * 36 + kk + tg]);
                fa[h][mi][1] = fbits(SA[(mb + 8 + g) * 36 + kk + tg]);
                fa[h][mi][2] = fbits(SA[(mb + g)     * 36 + kk + tg + 4]);
                fa[h][mi][3] = fbits(SA[(mb + 8 + g) * 36 + kk + tg + 4]);
            } else {
                fa[h][mi][0] = fbits(SA[(kk + tg)     * 264 + mb + g]);
                fa[h][mi][1] = fbits(SA[(kk + tg)     * 264 + mb + 8 + g]);
                fa[h][mi][2] = fbits(SA[(kk + tg + 4) * 264 + mb + g]);
                fa[h][mi][3] = fbits(SA[(kk + tg + 4) * 264 + mb + 8 + g]);
            }
        }
#pragma unroll
        for (int ni = 0; ni < 8; ni++) {
            int nb2 = wn * 64 + ni * 8;
            if (TB) {
                fb[h][ni][0] = fbits(SB[(nb2 + g) * 36 + kk + tg]);
                fb[h][ni][1] = fbits(SB[(nb2 + g) * 36 + kk + tg + 4]);
            } else {
                fb[h][ni][0] = fbits(SB[(kk + tg)     * 136 + nb2 + g]);
                fb[h][ni][1] = fbits(SB[(kk + tg + 4) * 136 + nb2 + g]);
            }
        }
    };

    issue(0, 0);
    issue(1, 1);

    int stage = 0;
    for (int t = 0; t < nsteps; t++) {
        asm volatile("cp.async.wait_group %0;" :: "n"(NSTAGE - 2) : "memory");
        __syncthreads();
        {
            int tn = t + 2;
            if (tn < nsteps) {
                int sn = stage + 2; if (sn >= NSTAGE) sn -= NSTAGE;
                issue(tn, sn);
            } else {
                asm volatile("cp.async.commit_group;" ::: "memory");
            }
        }

        const float* SA = (const float*)(smem + (size_t)stage * STG_A);
        const float* SB = (const float*)(smem + (size_t)NSTAGE * STG_A + (size_t)stage * STG_B);
        ldfrags(SA, SB, 0, 0);
#pragma unroll
        for (int h = 0; h < 4; h++) {
            if (h < 3) ldfrags(SA, SB, (h + 1) * 8, (h + 1) & 1);  // prefetch next half
            const int cb = h & 1;
#pragma unroll
            for (int ni = 0; ni < 8; ni++)
#pragma unroll
                for (int mi = 0; mi < 4; mi++)
                    mma8(acc[mi][ni], fa[cb][mi][0], fa[cb][mi][1],
                         fa[cb][mi][2], fa[cb][mi][3], fb[cb][ni][0], fb[cb][ni][1]);
        }
        if (++stage == NSTAGE) stage = 0;
    }

    // ---- epilogue ----
    float*       Cb = C + (size_t)bz * strideC;
    const float* Rb = resid    ? resid    + (size_t)bz * strideC : nullptr;
    const float* Cs = colscale ? colscale + (size_t)bz * NTOK    : nullptr;
#pragma unroll
    for (int mi = 0; mi < 4; mi++) {
#pragma unroll
        for (int half = 0; half < 2; half++) {
            int m = m0 + wm * 64 + mi * 16 + g + half * 8;
            float bv = bias ? bias[m] : 0.f;
#pragma unroll
            for (int ni = 0; ni < 8; ni++) {
                int n = n0 + wn * 64 + ni * 8 + tg * 2;
                float2 val;
                val.x = acc[mi][ni][half * 2 + 0] * scale + bv;
                val.y = acc[mi][ni][half * 2 + 1] * scale + bv;
                if (expOut) { val.x = __expf(val.x); val.y = __expf(val.y); }
                if (Cs) { val.x *= Cs[n]; val.y *= Cs[n + 1]; }
                if (Rb) {
                    val.x += Rb[(size_t)m * ldc + n];
                    val.y += Rb[(size_t)m * ldc + n + 1];
                }
                if (roundOut) { val.x = tf32r(val.x); val.y = tf32r(val.y); }
                *(float2*)&Cb[(size_t)m * ldc + n] = val;
            }
        }
    }
}

// ---------------- launch ----------------------------------------------------------
extern "C" void kernel_launch(void* const* d_in, const int* in_sizes, int n_in,
                              void* d_out, int out_size)
{
    const float* x     = (const float*)d_in[0];
    const float* gamma = (const float*)d_in[1];
    const float* beta  = (const float*)d_in[2];
    const float* wq    = (const float*)d_in[3];
    const float* bq    = (const float*)d_in[4];
    const float* wk    = (const float*)d_in[5];
    const float* bk    = (const float*)d_in[6];
    const float* wv    = (const float*)d_in[7];
    const float* bv    = (const float*)d_in[8];
    const float* wp    = (const float*)d_in[9];
    const float* bp    = (const float*)d_in[10];
    float* out = (float*)d_out;

    float *hn, *qkv, *s, *o, *w, *bqkv, *rinv;
    cudaGetSymbolAddress((void**)&hn,   g_hn);
    cudaGetSymbolAddress((void**)&qkv,  g_qkv);
    cudaGetSymbolAddress((void**)&s,    g_s);
    cudaGetSymbolAddress((void**)&o,    g_o);
    cudaGetSymbolAddress((void**)&w,    g_w);
    cudaGetSymbolAddress((void**)&bqkv, g_bqkv);
    cudaGetSymbolAddress((void**)&rinv, g_rinv);

    cudaFuncSetAttribute(gemm_cp<true,  false>, cudaFuncAttributeMaxDynamicSharedMemorySize, SMEM_TOTAL);
    cudaFuncSetAttribute(gemm_cp<false, false>, cudaFuncAttributeMaxDynamicSharedMemorySize, SMEM_TOTAL);
    cudaFuncSetAttribute(gemm_cp<true,  true >, cudaFuncAttributeMaxDynamicSharedMemorySize, SMEM_TOTAL);

    const long sBN  = (long)CH * NTOK;     // per-batch stride of (c, n) tensors
    const long sQKV = 3 * sBN;
    const long sS   = (long)NTOK * NTOK;

    // 0. setup
    round_weights<<<4 * CH * CH / 1024, 256>>>(wq, wk, wv, wp, w);
    stack_bias<<<1, 512>>>(bq, bk, bv, bqkv);

    // 1. GroupNorm -> hn (channel-major, tf32)
    groupnorm_kernel<<<BATCH * NGRP, 256>>>(x, gamma, beta, hn);

    // 2. fused QKV: C(1536 x 1024) = Wqkv(row-major, TA) x hn(k-major)
    gemm_cp<true,  false><<<dim3(NTOK / 128, 3 * CH / 256, BATCH), 256, SMEM_TOTAL>>>(
        w, 0, CH,  hn, sBN, NTOK,  qkv, sQKV, NTOK,
        CH, bqkv, nullptr, nullptr, 1.0f, 1, 0);

    // 3. e(n,m) = exp(q^T k * C^-0.5)   (softmax shift-invariant; logits O(10) -> no overflow)
    gemm_cp<false, false><<<dim3(NTOK / 128, NTOK / 256, BATCH), 256, SMEM_TOTAL>>>(
        qkv, sQKV, NTOK,  qkv + sBN, sQKV, NTOK,  s, sS, NTOK,
        CH, nullptr, nullptr, nullptr, 0.04419417382415922f, 1, 1);

    // 4. rinv[b][n] = 1 / sum_m e(n,m)
    rowsum_recip<<<BATCH * NTOK / 8, 256>>>(s, rinv);

    // 5. O(c,n) = V(c,m; TA) x e^T(n,m; TB) * rinv[n], K = 1024
    dim3 g_nn(NTOK / 128, CH / 256, BATCH);
    gemm_cp<true,  true ><<<g_nn, 256, SMEM_TOTAL>>>(
        qkv + 2 * sBN, sQKV, NTOK,  s, sS, NTOK,  o, sBN, NTOK,
        NTOK, nullptr, nullptr, rinv, 1.0f, 1, 0);

    // 6. out = Wp x o + bp + x
    gemm_cp<true,  false><<<g_nn, 256, SMEM_TOTAL>>>(
        w + 3 * CH * CH, 0, CH,  o, sBN, NTOK,  out, sBN, NTOK,
        CH, bp, x, nullptr, 1.0f, 0, 0);
}

// round 14
// speedup vs baseline: 1.6720x; 1.6720x over previous
#include <cuda_runtime.h>
#include <cuda_bf16.h>
#include <cstdint>

#define BATCH 32
#define CH    512
#define NGRP  16
#define CPG   32
#define NTOK  1024
#define GSIZE (CPG * NTOK)

#define NSTAGE 4
#define STG    10240                        // 128 rows x 80 B (32 bf16 + 8 pad)
#define SMEM_TOTAL (2 * NSTAGE * STG)       // 81920 B

typedef __nv_bfloat16 bf16;

// ---------------- scratch (static device globals; runtime alloc forbidden) -------
__device__ bf16  g_hn [(size_t)BATCH * NTOK * CH];       // (b, n, c) token-major
__device__ bf16  g_qk [(size_t)BATCH * NTOK * 2 * CH];   // (b, n, q|k) 1024 cols
__device__ bf16  g_v  [(size_t)BATCH * CH * NTOK];       // (b, c, m)
__device__ bf16  g_e  [(size_t)BATCH * NTOK * NTOK];     // exp(scores) (b, n, m)
__device__ bf16  g_ot [(size_t)BATCH * NTOK * CH];       // (b, n, c)
__device__ bf16  g_wb [4 * CH * CH];                     // bf16 wq|wk|wv|wp
__device__ float g_bqk[2 * CH];                          // stacked bq|bk
__device__ float g_rinv[(size_t)BATCH * NTOK];           // 1 / rowsum(exp)

// ---------------- helpers ---------------------------------------------------------
__device__ __forceinline__ uint32_t smem_u32(const void* p) {
    uint32_t a;
    asm("{ .reg .u64 t; cvta.to.shared.u64 t, %1; cvt.u32.u64 %0, t; }" : "=r"(a) : "l"(p));
    return a;
}
// pack (lo, hi) floats -> bf16x2 (rn)
__device__ __forceinline__ uint32_t pkbf(float lo, float hi) {
    uint32_t r;
    asm("cvt.rn.bf16x2.f32 %0, %1, %2;" : "=r"(r) : "f"(hi), "f"(lo));
    return r;
}
__device__ __forceinline__ void cpa16(uint32_t s, const void* g) {
    asm volatile("cp.async.cg.shared.global [%0], [%1], 16;" :: "r"(s), "l"(g));
}
__device__ __forceinline__ void mma16(float c[4],
    uint32_t a0, uint32_t a1, uint32_t a2, uint32_t a3, uint32_t b0, uint32_t b1)
{
    asm volatile(
        "mma.sync.aligned.m16n8k16.row.col.f32.bf16.bf16.f32 "
        "{%0,%1,%2,%3}, {%4,%5,%6,%7}, {%8,%9}, {%0,%1,%2,%3};"
        : "+f"(c[0]), "+f"(c[1]), "+f"(c[2]), "+f"(c[3])
        : "r"(a0), "r"(a1), "r"(a2), "r"(a3), "r"(b0), "r"(b1));
}

// ---------------- setup kernels ----------------------------------------------------
__global__ __launch_bounds__(256) void round_weights(
    const float* __restrict__ wq, const float* __restrict__ wk,
    const float* __restrict__ wv, const float* __restrict__ wp,
    bf16* __restrict__ w)
{
    int i = blockIdx.x * 256 + threadIdx.x;   // 4 * 65536 float4s
    int m = i >> 16, j = i & 65535;
    const float* src = (m == 0) ? wq : (m == 1) ? wk : (m == 2) ? wv : wp;
    float4 v = ((const float4*)src)[j];
    uint2 p = make_uint2(pkbf(v.x, v.y), pkbf(v.z, v.w));
    ((uint2*)(w + (size_t)m * CH * CH))[j] = p;
}
__global__ __launch_bounds__(512) void stack_bias(
    const float* __restrict__ bq, const float* __restrict__ bk,
    float* __restrict__ dst)
{
    int i = threadIdx.x;
    dst[i] = bq[i]; dst[CH + i] = bk[i];
}

// ---------------- GroupNorm + transpose: x(b,c,n) -> hn_t(b,n,c) bf16 -------------
__global__ __launch_bounds__(256) void groupnorm_t(
    const float* __restrict__ x, const float* __restrict__ gamma,
    const float* __restrict__ beta, bf16* __restrict__ hn)
{
    int b = blockIdx.x / NGRP, g = blockIdx.x % NGRP;
    const float* xp = x + ((size_t)b * CH + g * CPG) * NTOK;
    int tid = threadIdx.x;

    float s = 0.f, s2 = 0.f;
    for (int i = tid; i < GSIZE; i += 256) {
        float v = xp[i];
        s += v; s2 += v * v;
    }
    __shared__ float rs[256], rs2[256];
    rs[tid] = s; rs2[tid] = s2;
    __syncthreads();
    for (int o = 128; o > 0; o >>= 1) {
        if (tid < o) { rs[tid] += rs[tid + o]; rs2[tid] += rs2[tid + o]; }
        __syncthreads();
    }
    float mean = rs[0] * (1.0f / GSIZE);
    float var  = rs2[0] * (1.0f / GSIZE) - mean * mean;
    float rstd = rsqrtf(var + 1e-6f);
    __syncthreads();

    __shared__ float tile[32][33];
    int c = tid >> 3, q = tid & 7;
    float gj[4], bj[4];
#pragma unroll
    for (int j = 0; j < 4; j++) {
        int ch = g * CPG + q * 4 + j;
        gj[j] = gamma[ch]; bj[j] = beta[ch];
    }
    for (int t0 = 0; t0 < NTOK; t0 += 32) {
        float4 vv = *(const float4*)&xp[(size_t)c * NTOK + t0 + q * 4];
        tile[c][q * 4 + 0] = vv.x; tile[c][q * 4 + 1] = vv.y;
        tile[c][q * 4 + 2] = vv.z; tile[c][q * 4 + 3] = vv.w;
        __syncthreads();
        int tok = tid >> 3;
        float o0 = (tile[q * 4 + 0][tok] - mean) * rstd * gj[0] + bj[0];
        float o1 = (tile[q * 4 + 1][tok] - mean) * rstd * gj[1] + bj[1];
        float o2 = (tile[q * 4 + 2][tok] - mean) * rstd * gj[2] + bj[2];
        float o3 = (tile[q * 4 + 3][tok] - mean) * rstd * gj[3] + bj[3];
        uint2 p = make_uint2(pkbf(o0, o1), pkbf(o2, o3));
        *(uint2*)&hn[((size_t)b * NTOK + t0 + tok) * CH + g * CPG + q * 4] = p;
        __syncthreads();
    }
}

// ---------------- row sum of bf16 exp-scores -> reciprocal ------------------------
__global__ __launch_bounds__(256) void rowsum_recip(const bf16* __restrict__ e,
                                                    float* __restrict__ rinv)
{
    int row  = blockIdx.x * 8 + (threadIdx.x >> 5);   // one warp per row
    int lane = threadIdx.x & 31;
    const uint4* p = (const uint4*)(e + (size_t)row * NTOK);
    float s = 0.f;
#pragma unroll
    for (int j = 0; j < 4; j++) {
        uint4 u = p[lane + 32 * j];
        uint32_t w[4] = {u.x, u.y, u.z, u.w};
#pragma unroll
        for (int t = 0; t < 4; t++) {
            __nv_bfloat162 h = *(__nv_bfloat162*)&w[t];
            s += __bfloat162float(h.x) + __bfloat162float(h.y);
        }
    }
#pragma unroll
    for (int o = 16; o > 0; o >>= 1) s += __shfl_xor_sync(0xFFFFFFFFu, s, o);
    if (lane == 0) rinv[row] = 1.0f / s;
}

// ---------------- bf16 mma.sync batched GEMM (all operands row-major, K contig) ----
// C[bz](M x N) = A[M][K] x B[N][K]^T. Block tile 128x128, 8 warps 4x2 (32x64),
// K-step 32 = 2 x m16n8k16, 4-stage cp.async, fragment double-buffer.
__global__ __launch_bounds__(256, 2) void gemm_bf16(
    const bf16* __restrict__ A, long sA, int lda,
    const bf16* __restrict__ B, long sB, int ldb,
    void* __restrict__ Cv, long sC, int ldc,
    int K, const float* __restrict__ bias_row, const float* __restrict__ bias_col,
    const float* __restrict__ rowscale, const float* __restrict__ resid,
    float scale, int expOut, int f32Out)
{
    extern __shared__ char smem[];
    const uint32_t sbase = smem_u32(smem);

    const int bz = blockIdx.z;
    const int m0 = blockIdx.y * 128, n0 = blockIdx.x * 128;
    const bf16* Ab = A + (size_t)bz * sA;
    const bf16* Bb = B + (size_t)bz * sB;

    const int tid  = threadIdx.x;
    const int lane = tid & 31, warp = tid >> 5;
    const int wm = warp >> 1, wn = warp & 1;      // 4 x 2 warps, 32 x 64 tiles
    const int g  = lane >> 2, tg = lane & 3;

    float acc[2][8][4];
#pragma unroll
    for (int i = 0; i < 2; i++)
#pragma unroll
        for (int j = 0; j < 8; j++)
#pragma unroll
            for (int c = 0; c < 4; c++) acc[i][j][c] = 0.f;

    const int nsteps = K / 32;

    auto issue = [&](int step, int s) {
        const uint32_t sa  = sbase + s * STG;
        const uint32_t sbb = sbase + NSTAGE * STG + s * STG;
        const int k0 = step * 32;
#pragma unroll
        for (int i = 0; i < 2; i++) {             // each operand: 128 rows x 64B
            int idx = tid + i * 256;
            int m = idx >> 2, kq = idx & 3;
            cpa16(sa  + m * 80 + kq * 16, Ab + (size_t)(m0 + m) * lda + k0 + kq * 8);
            cpa16(sbb + m * 80 + kq * 16, Bb + (size_t)(n0 + m) * ldb + k0 + kq * 8);
        }
        asm volatile("cp.async.commit_group;" ::: "memory");
    };

    // fragment double buffers (two kk-16 halves in flight)
    uint32_t fa[2][2][4];
    uint32_t fb[2][8][2];

    auto ldfrags = [&](const uint32_t* SA32, const uint32_t* SB32, int kk2, int h) {
#pragma unroll
        for (int mi = 0; mi < 2; mi++) {
            int mb = wm * 32 + mi * 16;
            fa[h][mi][0] = SA32[(mb + g)     * 20 + kk2 + tg];
            fa[h][mi][1] = SA32[(mb + 8 + g) * 20 + kk2 + tg];
            fa[h][mi][2] = SA32[(mb + g)     * 20 + kk2 + 4 + tg];
            fa[h][mi][3] = SA32[(mb + 8 + g) * 20 + kk2 + 4 + tg];
        }
#pragma unroll
        for (int ni = 0; ni < 8; ni++) {
            int nb = wn * 64 + ni * 8;
            fb[h][ni][0] = SB32[(nb + g) * 20 + kk2 + tg];
            fb[h][ni][1] = SB32[(nb + g) * 20 + kk2 + 4 + tg];
        }
    };

    issue(0, 0); issue(1, 1); issue(2, 2);

    int stage = 0;
    for (int t = 0; t < nsteps; t++) {
        asm volatile("cp.async.wait_group %0;" :: "n"(NSTAGE - 2) : "memory");
        __syncthreads();
        {
            int tn = t + NSTAGE - 1;
            if (tn < nsteps) issue(tn, (stage + NSTAGE - 1) & (NSTAGE - 1));
            else asm volatile("cp.async.commit_group;" ::: "memory");
        }

        const uint32_t* SA32 = (const uint32_t*)(smem + (size_t)stage * STG);
        const uint32_t* SB32 = (const uint32_t*)(smem + (size_t)NSTAGE * STG
                                                      + (size_t)stage * STG);
        ldfrags(SA32, SB32, 0, 0);
#pragma unroll
        for (int h = 0; h < 2; h++) {
            if (h == 0) ldfrags(SA32, SB32, 8, 1);   // prefetch half 1
#pragma unroll
            for (int ni = 0; ni < 8; ni++) {
                mma16(acc[0][ni], fa[h][0][0], fa[h][0][1], fa[h][0][2], fa[h][0][3],
                      fb[h][ni][0], fb[h][ni][1]);
                mma16(acc[1][ni], fa[h][1][0], fa[h][1][1], fa[h][1][2], fa[h][1][3],
                      fb[h][ni][0], fb[h][ni][1]);
            }
        }
        stage = (stage + 1) & (NSTAGE - 1);
    }

    // ---- epilogue ----
    const float* Rs = rowscale ? rowscale + (size_t)bz * NTOK : nullptr;
    const float* Rb = resid    ? resid    + (size_t)bz * sC   : nullptr;
#pragma unroll
    for (int mi = 0; mi < 2; mi++) {
#pragma unroll
        for (int half = 0; half < 2; half++) {
            int m = m0 + wm * 32 + mi * 16 + g + half * 8;
            float bv = bias_row ? bias_row[m] : 0.f;
            float rf = Rs ? Rs[m] : 1.f;
#pragma unroll
            for (int ni = 0; ni < 8; ni++) {
                int n = n0 + wn * 64 + ni * 8 + tg * 2;
                float vx = acc[mi][ni][half * 2 + 0] * scale;
                float vy = acc[mi][ni][half * 2 + 1] * scale;
                if (expOut) { vx = __expf(vx); vy = __expf(vy); }
                vx += bv; vy += bv;
                if (bias_col) { vx += bias_col[n]; vy += bias_col[n + 1]; }
                vx *= rf; vy *= rf;
                if (Rb) {
                    vx += Rb[(size_t)m * ldc + n];
                    vy += Rb[(size_t)m * ldc + n + 1];
                }
                if (f32Out) {
                    float* Cf = (float*)Cv + (size_t)bz * sC;
                    *(float2*)&Cf[(size_t)m * ldc + n] = make_float2(vx, vy);
                } else {
                    bf16* Cb = (bf16*)Cv + (size_t)bz * sC;
                    *(uint32_t*)&Cb[(size_t)m * ldc + n] = pkbf(vx, vy);
                }
            }
        }
    }
}

// ---------------- launch ----------------------------------------------------------
extern "C" void kernel_launch(void* const* d_in, const int* in_sizes, int n_in,
                              void* d_out, int out_size)
{
    const float* x     = (const float*)d_in[0];
    const float* gamma = (const float*)d_in[1];
    const float* beta  = (const float*)d_in[2];
    const float* wq    = (const float*)d_in[3];
    const float* bq    = (const float*)d_in[4];
    const float* wk    = (const float*)d_in[5];
    const float* bk    = (const float*)d_in[6];
    const float* wv    = (const float*)d_in[7];
    const float* bv    = (const float*)d_in[8];
    const float* wp    = (const float*)d_in[9];
    const float* bp    = (const float*)d_in[10];
    float* out = (float*)d_out;

    bf16 *hn, *qk, *v, *e, *ot, *wb;
    float *bqk, *rinv;
    cudaGetSymbolAddress((void**)&hn,   g_hn);
    cudaGetSymbolAddress((void**)&qk,   g_qk);
    cudaGetSymbolAddress((void**)&v,    g_v);
    cudaGetSymbolAddress((void**)&e,    g_e);
    cudaGetSymbolAddress((void**)&ot,   g_ot);
    cudaGetSymbolAddress((void**)&wb,   g_wb);
    cudaGetSymbolAddress((void**)&bqk,  g_bqk);
    cudaGetSymbolAddress((void**)&rinv, g_rinv);

    cudaFuncSetAttribute(gemm_bf16, cudaFuncAttributeMaxDynamicSharedMemorySize, SMEM_TOTAL);

    const long sTC = (long)NTOK * CH;      // (n, c) per-batch stride
    const long sQK = (long)NTOK * 2 * CH;  // (n, 1024)
    const long sCT = (long)CH * NTOK;      // (c, m)
    const long sS  = (long)NTOK * NTOK;

    // 0. setup
    round_weights<<<4 * CH * CH / 1024, 256>>>(wq, wk, wv, wp, wb);
    stack_bias<<<1, 512>>>(bq, bk, bqk);

    // 1. GroupNorm -> hn_t (b, n, c) bf16
    groupnorm_t<<<BATCH * NGRP, 256>>>(x, gamma, beta, hn);

    // 2. fused q|k: C(n, 1024) = hn_t(n,c) x [Wq;Wk](oc,c)^T + [bq;bk]
    gemm_bf16<<<dim3(8, 8, BATCH), 256, SMEM_TOTAL>>>(
        hn, sTC, CH,  wb, 0, CH,  qk, sQK, 2 * CH,
        CH, nullptr, bqk, nullptr, nullptr, 1.0f, 0, 0);

    // 3. v(c, m) = Wv(oc,c) x hn_t(m,c)^T + bv
    gemm_bf16<<<dim3(8, 4, BATCH), 256, SMEM_TOTAL>>>(
        wb + 2 * CH * CH, 0, CH,  hn, sTC, CH,  v, sCT, NTOK,
        CH, bv, nullptr, nullptr, nullptr, 1.0f, 0, 0);

    // 4. e(n, m) = exp(q(n,c) x k(m,c)^T * C^-0.5)
    gemm_bf16<<<dim3(8, 8, BATCH), 256, SMEM_TOTAL>>>(
        qk, sQK, 2 * CH,  qk + CH, sQK, 2 * CH,  e, sS, NTOK,
        CH, nullptr, nullptr, nullptr, nullptr, 0.04419417382415922f, 1, 0);

    // 5. rinv[b][n] = 1 / sum_m e(n,m)
    rowsum_recip<<<BATCH * NTOK / 8, 256>>>(e, rinv);

    // 6. o_t(n, c) = [e(n,m) x v(c,m)^T] * rinv[n]
    gemm_bf16<<<dim3(4, 8, BATCH), 256, SMEM_TOTAL>>>(
        e, sS, NTOK,  v, sCT, NTOK,  ot, sTC, CH,
        NTOK, nullptr, nullptr, rinv, nullptr, 1.0f, 0, 0);

    // 7. out(c, n) = Wp(oc,c) x o_t(n,c)^T + bp + x   (fp32 out)
    gemm_bf16<<<dim3(8, 4, BATCH), 256, SMEM_TOTAL>>>(
        wb + 3 * CH * CH, 0, CH,  ot, sTC, CH,  out, sCT, NTOK,
        CH, bp, nullptr, nullptr, x, 1.0f, 0, 1);
}

// round 16
// speedup vs baseline: 1.7946x; 1.0734x over previous
#include <cuda_runtime.h>
#include <cuda_bf16.h>
#include <cstdint>

#define BATCH 32
#define CH    512
#define NGRP  16
#define CPG   32
#define NTOK  1024
#define GSIZE (CPG * NTOK)

#define NSTAGE 4
#define STG    10240                        // 128 rows x 80 B (32 bf16 + 8 pad)
#define SMEM_TOTAL (2 * NSTAGE * STG)       // 81920 B

typedef __nv_bfloat16 bf16;

// ---------------- scratch (static device globals; runtime alloc forbidden) -------
__device__ bf16  g_hn [(size_t)BATCH * NTOK * CH];       // (b, n, c) token-major
__device__ bf16  g_qk [(size_t)BATCH * NTOK * 2 * CH];   // (b, n, q|k) 1024 cols
__device__ bf16  g_v  [(size_t)BATCH * CH * NTOK];       // (b, c, m)
__device__ bf16  g_e  [(size_t)BATCH * NTOK * NTOK];     // exp(scores) (b, n, m)
__device__ bf16  g_ot [(size_t)BATCH * NTOK * CH];       // (b, n, c)
__device__ bf16  g_wb [4 * CH * CH];                     // bf16 wq|wk|wv|wp
__device__ float g_bqk[2 * CH];                          // stacked bq|bk
__device__ float g_rinv[(size_t)BATCH * NTOK];           // 1 / rowsum(exp)

// ---------------- helpers ---------------------------------------------------------
__device__ __forceinline__ uint32_t smem_u32(const void* p) {
    uint32_t a;
    asm("{ .reg .u64 t; cvta.to.shared.u64 t, %1; cvt.u32.u64 %0, t; }" : "=r"(a) : "l"(p));
    return a;
}
// pack (lo, hi) floats -> bf16x2 (rn)
__device__ __forceinline__ uint32_t pkbf(float lo, float hi) {
    uint32_t r;
    asm("cvt.rn.bf16x2.f32 %0, %1, %2;" : "=r"(r) : "f"(hi), "f"(lo));
    return r;
}
__device__ __forceinline__ void cpa16(uint32_t s, const void* g) {
    asm volatile("cp.async.cg.shared.global [%0], [%1], 16;" :: "r"(s), "l"(g));
}
__device__ __forceinline__ void mma16(float c[4],
    uint32_t a0, uint32_t a1, uint32_t a2, uint32_t a3, uint32_t b0, uint32_t b1)
{
    asm volatile(
        "mma.sync.aligned.m16n8k16.row.col.f32.bf16.bf16.f32 "
        "{%0,%1,%2,%3}, {%4,%5,%6,%7}, {%8,%9}, {%0,%1,%2,%3};"
        : "+f"(c[0]), "+f"(c[1]), "+f"(c[2]), "+f"(c[3])
        : "r"(a0), "r"(a1), "r"(a2), "r"(a3), "r"(b0), "r"(b1));
}
__device__ __forceinline__ void ldsm4(uint32_t& r0, uint32_t& r1, uint32_t& r2,
                                      uint32_t& r3, uint32_t addr)
{
    asm volatile("ldmatrix.sync.aligned.m8n8.x4.shared.b16 {%0,%1,%2,%3}, [%4];"
        : "=r"(r0), "=r"(r1), "=r"(r2), "=r"(r3) : "r"(addr));
}

// ---------------- setup kernels ----------------------------------------------------
__global__ __launch_bounds__(256) void round_weights(
    const float* __restrict__ wq, const float* __restrict__ wk,
    const float* __restrict__ wv, const float* __restrict__ wp,
    bf16* __restrict__ w)
{
    int i = blockIdx.x * 256 + threadIdx.x;   // 4 * 65536 float4s
    int m = i >> 16, j = i & 65535;
    const float* src = (m == 0) ? wq : (m == 1) ? wk : (m == 2) ? wv : wp;
    float4 v = ((const float4*)src)[j];
    uint2 p = make_uint2(pkbf(v.x, v.y), pkbf(v.z, v.w));
    ((uint2*)(w + (size_t)m * CH * CH))[j] = p;
}
__global__ __launch_bounds__(512) void stack_bias(
    const float* __restrict__ bq, const float* __restrict__ bk,
    float* __restrict__ dst)
{
    int i = threadIdx.x;
    dst[i] = bq[i]; dst[CH + i] = bk[i];
}

// ---------------- GroupNorm + transpose: x(b,c,n) -> hn_t(b,n,c) bf16 -------------
__global__ __launch_bounds__(256) void groupnorm_t(
    const float* __restrict__ x, const float* __restrict__ gamma,
    const float* __restrict__ beta, bf16* __restrict__ hn)
{
    int b = blockIdx.x / NGRP, g = blockIdx.x % NGRP;
    const float* xp = x + ((size_t)b * CH + g * CPG) * NTOK;
    int tid = threadIdx.x;

    float s = 0.f, s2 = 0.f;
    for (int i = tid; i < GSIZE; i += 256) {
        float v = xp[i];
        s += v; s2 += v * v;
    }
    __shared__ float rs[256], rs2[256];
    rs[tid] = s; rs2[tid] = s2;
    __syncthreads();
    for (int o = 128; o > 0; o >>= 1) {
        if (tid < o) { rs[tid] += rs[tid + o]; rs2[tid] += rs2[tid + o]; }
        __syncthreads();
    }
    float mean = rs[0] * (1.0f / GSIZE);
    float var  = rs2[0] * (1.0f / GSIZE) - mean * mean;
    float rstd = rsqrtf(var + 1e-6f);
    __syncthreads();

    __shared__ float tile[32][33];
    int c = tid >> 3, q = tid & 7;
    float gj[4], bj[4];
#pragma unroll
    for (int j = 0; j < 4; j++) {
        int ch = g * CPG + q * 4 + j;
        gj[j] = gamma[ch]; bj[j] = beta[ch];
    }
    for (int t0 = 0; t0 < NTOK; t0 += 32) {
        float4 vv = *(const float4*)&xp[(size_t)c * NTOK + t0 + q * 4];
        tile[c][q * 4 + 0] = vv.x; tile[c][q * 4 + 1] = vv.y;
        tile[c][q * 4 + 2] = vv.z; tile[c][q * 4 + 3] = vv.w;
        __syncthreads();
        int tok = tid >> 3;
        float o0 = (tile[q * 4 + 0][tok] - mean) * rstd * gj[0] + bj[0];
        float o1 = (tile[q * 4 + 1][tok] - mean) * rstd * gj[1] + bj[1];
        float o2 = (tile[q * 4 + 2][tok] - mean) * rstd * gj[2] + bj[2];
        float o3 = (tile[q * 4 + 3][tok] - mean) * rstd * gj[3] + bj[3];
        uint2 p = make_uint2(pkbf(o0, o1), pkbf(o2, o3));
        *(uint2*)&hn[((size_t)b * NTOK + t0 + tok) * CH + g * CPG + q * 4] = p;
        __syncthreads();
    }
}

// ---------------- row sum of bf16 exp-scores -> reciprocal ------------------------
__global__ __launch_bounds__(256) void rowsum_recip(const bf16* __restrict__ e,
                                                    float* __restrict__ rinv)
{
    int row  = blockIdx.x * 8 + (threadIdx.x >> 5);   // one warp per row
    int lane = threadIdx.x & 31;
    const uint4* p = (const uint4*)(e + (size_t)row * NTOK);
    float s = 0.f;
#pragma unroll
    for (int j = 0; j < 4; j++) {
        uint4 u = p[lane + 32 * j];
        uint32_t w[4] = {u.x, u.y, u.z, u.w};
#pragma unroll
        for (int t = 0; t < 4; t++) {
            __nv_bfloat162 h = *(__nv_bfloat162*)&w[t];
            s += __bfloat162float(h.x) + __bfloat162float(h.y);
        }
    }
#pragma unroll
    for (int o = 16; o > 0; o >>= 1) s += __shfl_xor_sync(0xFFFFFFFFu, s, o);
    if (lane == 0) rinv[row] = 1.0f / s;
}

// ---------------- bf16 mma.sync batched GEMM (all operands row-major, K contig) ----
// C[bz](M x N) = A[M][K] x B[N][K]^T. Block tile 128x128, 8 warps 4x2 (32x64),
// K-step 32 = 2 x m16n8k16, 4-stage cp.async, ldmatrix fragments, frag double-buffer.
__global__ __launch_bounds__(256, 2) void gemm_bf16(
    const bf16* __restrict__ A, long sA, int lda,
    const bf16* __restrict__ B, long sB, int ldb,
    void* __restrict__ Cv, long sC, int ldc,
    int K, const float* __restrict__ bias_row, const float* __restrict__ bias_col,
    const float* __restrict__ rowscale, const float* __restrict__ resid,
    float scale, int expOut, int f32Out)
{
    extern __shared__ char smem[];
    const uint32_t sbase = smem_u32(smem);

    const int bz = blockIdx.z;
    const int m0 = blockIdx.y * 128, n0 = blockIdx.x * 128;
    const bf16* Ab = A + (size_t)bz * sA;
    const bf16* Bb = B + (size_t)bz * sB;

    const int tid  = threadIdx.x;
    const int lane = tid & 31, warp = tid >> 5;
    const int wm = warp >> 1, wn = warp & 1;      // 4 x 2 warps, 32 x 64 tiles
    const int g  = lane >> 2, tg = lane & 3;

    // ldmatrix per-lane row/k-offset mapping (byte offsets within a stage)
    // A x4: mats 0,1 = rows +0..7 / +8..15 at k-lo; mats 2,3 = same rows at k-hi
    const int arow  = wm * 32 + (lane & 7) + ((lane >> 3) & 1) * 8;
    const int akoff = ((lane >> 4) & 1) * 8;          // bf16 elements
    // B x4 (ni pair): mats 0,1 = rows ni+0..7 at k-lo/k-hi; mats 2,3 = rows ni+8..15
    const int brow  = wn * 64 + (lane & 7) + ((lane >> 4) & 1) * 8;
    const int bkoff = ((lane >> 3) & 1) * 8;

    float acc[2][8][4];
#pragma unroll
    for (int i = 0; i < 2; i++)
#pragma unroll
        for (int j = 0; j < 8; j++)
#pragma unroll
            for (int c = 0; c < 4; c++) acc[i][j][c] = 0.f;

    const int nsteps = K / 32;

    auto issue = [&](int step, int s) {
        const uint32_t sa  = sbase + s * STG;
        const uint32_t sbb = sbase + NSTAGE * STG + s * STG;
        const int k0 = step * 32;
#pragma unroll
        for (int i = 0; i < 2; i++) {             // each operand: 128 rows x 64B
            int idx = tid + i * 256;
            int m = idx >> 2, kq = idx & 3;
            cpa16(sa  + m * 80 + kq * 16, Ab + (size_t)(m0 + m) * lda + k0 + kq * 8);
            cpa16(sbb + m * 80 + kq * 16, Bb + (size_t)(n0 + m) * ldb + k0 + kq * 8);
        }
        asm volatile("cp.async.commit_group;" ::: "memory");
    };

    // fragment double buffers (two kk-16 halves in flight)
    uint32_t fa[2][2][4];
    uint32_t fb[2][8][2];

    auto ldfrags = [&](uint32_t saddr, uint32_t baddr, int kk, int h) {
#pragma unroll
        for (int mi = 0; mi < 2; mi++)
            ldsm4(fa[h][mi][0], fa[h][mi][1], fa[h][mi][2], fa[h][mi][3],
                  saddr + (uint32_t)(arow + mi * 16) * 80 + (uint32_t)(kk + akoff) * 2);
#pragma unroll
        for (int j = 0; j < 4; j++)
            ldsm4(fb[h][2 * j][0], fb[h][2 * j][1], fb[h][2 * j + 1][0], fb[h][2 * j + 1][1],
                  baddr + (uint32_t)(brow + j * 16) * 80 + (uint32_t)(kk + bkoff) * 2);
    };

    issue(0, 0); issue(1, 1); issue(2, 2);

    int stage = 0;
    for (int t = 0; t < nsteps; t++) {
        asm volatile("cp.async.wait_group %0;" :: "n"(NSTAGE - 2) : "memory");
        __syncthreads();
        {
            int tn = t + NSTAGE - 1;
            if (tn < nsteps) issue(tn, (stage + NSTAGE - 1) & (NSTAGE - 1));
            else asm volatile("cp.async.commit_group;" ::: "memory");
        }

        const uint32_t sa  = sbase + (uint32_t)stage * STG;
        const uint32_t sbb = sbase + NSTAGE * STG + (uint32_t)stage * STG;
        ldfrags(sa, sbb, 0, 0);
#pragma unroll
        for (int h = 0; h < 2; h++) {
            if (h == 0) ldfrags(sa, sbb, 16, 1);   // prefetch half 1 under half-0 MMAs
#pragma unroll
            for (int ni = 0; ni < 8; ni++) {
                mma16(acc[0][ni], fa[h][0][0], fa[h][0][1], fa[h][0][2], fa[h][0][3],
                      fb[h][ni][0], fb[h][ni][1]);
                mma16(acc[1][ni], fa[h][1][0], fa[h][1][1], fa[h][1][2], fa[h][1][3],
                      fb[h][ni][0], fb[h][ni][1]);
            }
        }
        stage = (stage + 1) & (NSTAGE - 1);
    }

    // ---- epilogue ----
    const float* Rs = rowscale ? rowscale + (size_t)bz * NTOK : nullptr;
    const float* Rb = resid    ? resid    + (size_t)bz * sC   : nullptr;
#pragma unroll
    for (int mi = 0; mi < 2; mi++) {
#pragma unroll
        for (int half = 0; half < 2; half++) {
            int m = m0 + wm * 32 + mi * 16 + g + half * 8;
            float bv = bias_row ? bias_row[m] : 0.f;
            float rf = Rs ? Rs[m] : 1.f;
#pragma unroll
            for (int ni = 0; ni < 8; ni++) {
                int n = n0 + wn * 64 + ni * 8 + tg * 2;
                float vx = acc[mi][ni][half * 2 + 0] * scale;
                float vy = acc[mi][ni][half * 2 + 1] * scale;
                if (expOut) { vx = __expf(vx); vy = __expf(vy); }
                vx += bv; vy += bv;
                if (bias_col) { vx += bias_col[n]; vy += bias_col[n + 1]; }
                vx *= rf; vy *= rf;
                if (Rb) {
                    vx += Rb[(size_t)m * ldc + n];
                    vy += Rb[(size_t)m * ldc + n + 1];
                }
                if (f32Out) {
                    float* Cf = (float*)Cv + (size_t)bz * sC;
                    *(float2*)&Cf[(size_t)m * ldc + n] = make_float2(vx, vy);
                } else {
                    bf16* Cb = (bf16*)Cv + (size_t)bz * sC;
                    *(uint32_t*)&Cb[(size_t)m * ldc + n] = pkbf(vx, vy);
                }
            }
        }
    }
}

// ---------------- launch ----------------------------------------------------------
extern "C" void kernel_launch(void* const* d_in, const int* in_sizes, int n_in,
                              void* d_out, int out_size)
{
    const float* x     = (const float*)d_in[0];
    const float* gamma = (const float*)d_in[1];
    const float* beta  = (const float*)d_in[2];
    const float* wq    = (const float*)d_in[3];
    const float* bq    = (const float*)d_in[4];
    const float* wk    = (const float*)d_in[5];
    const float* bk    = (const float*)d_in[6];
    const float* wv    = (const float*)d_in[7];
    const float* bv    = (const float*)d_in[8];
    const float* wp    = (const float*)d_in[9];
    const float* bp    = (const float*)d_in[10];
    float* out = (float*)d_out;

    bf16 *hn, *qk, *v, *e, *ot, *wb;
    float *bqk, *rinv;
    cudaGetSymbolAddress((void**)&hn,   g_hn);
    cudaGetSymbolAddress((void**)&qk,   g_qk);
    cudaGetSymbolAddress((void**)&v,    g_v);
    cudaGetSymbolAddress((void**)&e,    g_e);
    cudaGetSymbolAddress((void**)&ot,   g_ot);
    cudaGetSymbolAddress((void**)&wb,   g_wb);
    cudaGetSymbolAddress((void**)&bqk,  g_bqk);
    cudaGetSymbolAddress((void**)&rinv, g_rinv);

    cudaFuncSetAttribute(gemm_bf16, cudaFuncAttributeMaxDynamicSharedMemorySize, SMEM_TOTAL);

    const long sTC = (long)NTOK * CH;      // (n, c) per-batch stride
    const long sQK = (long)NTOK * 2 * CH;  // (n, 1024)
    const long sCT = (long)CH * NTOK;      // (c, m)
    const long sS  = (long)NTOK * NTOK;

    // 0. setup
    round_weights<<<4 * CH * CH / 1024, 256>>>(wq, wk, wv, wp, wb);
    stack_bias<<<1, 512>>>(bq, bk, bqk);

    // 1. GroupNorm -> hn_t (b, n, c) bf16
    groupnorm_t<<<BATCH * NGRP, 256>>>(x, gamma, beta, hn);

    // 2. fused q|k: C(n, 1024) = hn_t(n,c) x [Wq;Wk](oc,c)^T + [bq;bk]
    gemm_bf16<<<dim3(8, 8, BATCH), 256, SMEM_TOTAL>>>(
        hn, sTC, CH,  wb, 0, CH,  qk, sQK, 2 * CH,
        CH, nullptr, bqk, nullptr, nullptr, 1.0f, 0, 0);

    // 3. v(c, m) = Wv(oc,c) x hn_t(m,c)^T + bv
    gemm_bf16<<<dim3(8, 4, BATCH), 256, SMEM_TOTAL>>>(
        wb + 2 * CH * CH, 0, CH,  hn, sTC, CH,  v, sCT, NTOK,
        CH, bv, nullptr, nullptr, nullptr, 1.0f, 0, 0);

    // 4. e(n, m) = exp(q(n,c) x k(m,c)^T * C^-0.5)
    gemm_bf16<<<dim3(8, 8, BATCH), 256, SMEM_TOTAL>>>(
        qk, sQK, 2 * CH,  qk + CH, sQK, 2 * CH,  e, sS, NTOK,
        CH, nullptr, nullptr, nullptr, nullptr, 0.04419417382415922f, 1, 0);

    // 5. rinv[b][n] = 1 / sum_m e(n,m)
    rowsum_recip<<<BATCH * NTOK / 8, 256>>>(e, rinv);

    // 6. o_t(n, c) = [e(n,m) x v(c,m)^T] * rinv[n]
    gemm_bf16<<<dim3(4, 8, BATCH), 256, SMEM_TOTAL>>>(
        e, sS, NTOK,  v, sCT, NTOK,  ot, sTC, CH,
        NTOK, nullptr, nullptr, rinv, nullptr, 1.0f, 0, 0);

    // 7. out(c, n) = Wp(oc,c) x o_t(n,c)^T + bp + x   (fp32 out)
    gemm_bf16<<<dim3(8, 4, BATCH), 256, SMEM_TOTAL>>>(
        wb + 3 * CH * CH, 0, CH,  ot, sTC, CH,  out, sCT, NTOK,
        CH, bp, nullptr, nullptr, x, 1.0f, 0, 1);
}